// round 1
// baseline (speedup 1.0000x reference)
#include <cuda_runtime.h>
#include <math.h>

// Problem constants
#define GRIDSZ 16
#define NB   4
#define NH   66
#define NW   66
#define NC   32
#define NF   64
#define HO   64
#define WO   64
#define CKK  288          // C*KH*KW = 32*9

// Scratch (device globals; no allocation allowed)
// AD table: [cij][g][f] -> (A, D) interleaved floats. cij=288, g=16, f=64.
__device__ __align__(16) float  g_AD[CKK * 16 * NF * 2];   // 2.36 MB
__device__ __align__(16) float  g_WS[CKK * NF];            // transposed w_silu [cij][f]
__device__ __align__(16) float4 g_feat[NB * NH * NW * NC]; // (t, silu, byteofs(g*512), 0)

// ---------------------------------------------------------------------------
// P0: build AD table.  tid -> f (6b), g (4b), cij (rest)
__global__ void build_ad_kernel(const float* __restrict__ cp,
                                const float* __restrict__ w_spline)
{
    int tid = blockIdx.x * blockDim.x + threadIdx.x;
    if (tid >= CKK * 16 * NF) return;
    int f   = tid & 63;
    int g   = (tid >> 6) & 15;
    int cij = tid >> 10;
    float ws = w_spline[f * CKK + cij];
    const float* cpp = cp + (size_t)f * (CKK * 17) + cij * 17 + g;
    float a0 = ws * cpp[0];
    float a1 = ws * cpp[1];
    g_AD[2 * tid]     = a0;
    g_AD[2 * tid + 1] = a1 - a0;
}

// P0b: transpose w_silu into [cij][f]
__global__ void build_ws_kernel(const float* __restrict__ w_silu)
{
    int tid = blockIdx.x * blockDim.x + threadIdx.x;
    if (tid >= CKK * NF) return;
    int f   = tid & 63;
    int cij = tid >> 6;
    g_WS[cij * NF + f] = w_silu[f * CKK + cij];
}

// ---------------------------------------------------------------------------
// P1: per-input-element features: t, silu(x), byte offset g*512 into AD slice
__global__ void feat_kernel(const float* __restrict__ x)
{
    int i = blockIdx.x * blockDim.x + threadIdx.x;
    if (i >= NB * NH * NW * NC) return;
    float v  = x[i];
    float s  = v / (1.0f + __expf(-v));                 // SiLU
    float xc = fminf(1.0f, fmaxf(-1.0f, v));
    float u  = (xc + 1.0f) * 8.0f;                      // / (2/16)
    int   g  = (int)u;
    g = (g > 15) ? 15 : g;
    float t  = u - (float)g;
    g_feat[i] = make_float4(t, s, __int_as_float(g * 512), 0.0f);
}

// ---------------------------------------------------------------------------
// Main kernel: 128 blocks x 256 threads.
// Block -> (b, 8-row h tile, 16-col w tile). Warp -> one output row, all 64 f.
// Thread (lane l) owns filters f = 2l, 2l+1.
__global__ __launch_bounds__(256, 1)
void kan_main_kernel(const float* __restrict__ bias,
                     float* __restrict__ out)
{
    int bx   = blockIdx.x;
    int b    = bx >> 5;                 // 32 blocks per batch image
    int h0   = ((bx >> 2) & 7) * 8;
    int w0   = (bx & 3) * 16;
    int warp = threadIdx.x >> 5;
    int lane = threadIdx.x & 31;
    int h    = h0 + warp;

    float acc0[16], acc1[16];
#pragma unroll
    for (int p = 0; p < 16; p++) { acc0[p] = 0.0f; acc1[p] = 0.0f; }

    const float4* feat = g_feat;

    for (int c = 0; c < NC; c++) {
#pragma unroll
        for (int i = 0; i < 3; i++) {
            const float4* frow = feat + ((b * NH + h + i) * NW + w0) * NC + c;
#pragma unroll
            for (int j = 0; j < 3; j++) {
                int cij = c * 9 + i * 3 + j;
                const char* adbase =
                    (const char*)g_AD + (size_t)cij * (16 * 512) + lane * 16;
                float2 wsv = *(const float2*)(g_WS + cij * NF + 2 * lane);
                const float4* fp = frow + j * NC;
#pragma unroll
                for (int p = 0; p < 16; p++) {
                    float4 us = __ldg(fp + p * NC);      // (t, s, ofs, -) broadcast
                    const float4 ad =
                        *(const float4*)(adbase + __float_as_int(us.z));
                    // spline: A + t*D for the two owned filters
                    acc0[p] += fmaf(us.x, ad.y, ad.x);
                    acc1[p] += fmaf(us.x, ad.w, ad.z);
                    // silu branch
                    acc0[p] = fmaf(us.y, wsv.x, acc0[p]);
                    acc1[p] = fmaf(us.y, wsv.y, acc1[p]);
                }
            }
        }
    }

    float2 bv = *(const float2*)(bias + 2 * lane);
    float* op = out + (((b * HO) + h) * WO + w0) * NF + 2 * lane;
#pragma unroll
    for (int p = 0; p < 16; p++) {
        float2 r;
        r.x = acc0[p] + bv.x;
        r.y = acc1[p] + bv.y;
        *(float2*)(op + p * NF) = r;
    }
}

// ---------------------------------------------------------------------------
extern "C" void kernel_launch(void* const* d_in, const int* in_sizes, int n_in,
                              void* d_out, int out_size)
{
    const float* x    = (const float*)d_in[0];   // (4,66,66,32)
    const float* cp   = (const float*)d_in[1];   // (64,32,3,3,17)
    const float* wsp  = (const float*)d_in[2];   // (64,32,3,3)
    const float* wsi  = (const float*)d_in[3];   // (64,32,3,3)
    const float* bias = (const float*)d_in[4];   // (64,)
    float* out        = (float*)d_out;           // (4,64,64,64)

    {
        int n = CKK * 16 * NF;
        build_ad_kernel<<<(n + 255) / 256, 256>>>(cp, wsp);
    }
    {
        int n = CKK * NF;
        build_ws_kernel<<<(n + 255) / 256, 256>>>(wsi);
    }
    {
        int n = NB * NH * NW * NC;
        feat_kernel<<<(n + 255) / 256, 256>>>(x);
    }
    kan_main_kernel<<<128, 256>>>(bias, out);
}

// round 2
// speedup vs baseline: 1.0014x; 1.0014x over previous
#include <cuda_runtime.h>
#include <math.h>

// Problem constants
#define GRIDSZ 16
#define NB   4
#define NH   66
#define NW   66
#define NC   32
#define NF   64
#define HO   64
#define WO   64
#define CKK  288          // C*KH*KW = 32*9

// Scratch (device globals; no allocation allowed)
// AD table: [cij][g][f] -> (A, D) interleaved floats. cij=288, g=16, f=64.
__device__ __align__(16) float  g_AD[CKK * 16 * NF * 2];   // 2.36 MB
__device__ __align__(16) float  g_WS[CKK * NF];            // transposed w_silu [cij][f]
__device__ __align__(16) float4 g_feat[NB * NH * NW * NC]; // (t, silu, byteofs(g*512), 0)

// ---------------------------------------------------------------------------
// P0: build AD table.  tid -> f (6b), g (4b), cij (rest)
__global__ void build_ad_kernel(const float* __restrict__ cp,
                                const float* __restrict__ w_spline)
{
    int tid = blockIdx.x * blockDim.x + threadIdx.x;
    if (tid >= CKK * 16 * NF) return;
    int f   = tid & 63;
    int g   = (tid >> 6) & 15;
    int cij = tid >> 10;
    float ws = w_spline[f * CKK + cij];
    const float* cpp = cp + (size_t)f * (CKK * 17) + cij * 17 + g;
    float a0 = ws * cpp[0];
    float a1 = ws * cpp[1];
    g_AD[2 * tid]     = a0;
    g_AD[2 * tid + 1] = a1 - a0;
}

// P0b: transpose w_silu into [cij][f]
__global__ void build_ws_kernel(const float* __restrict__ w_silu)
{
    int tid = blockIdx.x * blockDim.x + threadIdx.x;
    if (tid >= CKK * NF) return;
    int f   = tid & 63;
    int cij = tid >> 6;
    g_WS[cij * NF + f] = w_silu[f * CKK + cij];
}

// ---------------------------------------------------------------------------
// P1: per-input-element features: t, silu(x), byte offset g*512 into AD slice
__global__ void feat_kernel(const float* __restrict__ x)
{
    int i = blockIdx.x * blockDim.x + threadIdx.x;
    if (i >= NB * NH * NW * NC) return;
    float v  = x[i];
    float s  = v / (1.0f + __expf(-v));                 // SiLU
    float xc = fminf(1.0f, fmaxf(-1.0f, v));
    float u  = (xc + 1.0f) * 8.0f;                      // / (2/16)
    int   g  = (int)u;
    g = (g > 15) ? 15 : g;
    float t  = u - (float)g;
    g_feat[i] = make_float4(t, s, __int_as_float(g * 512), 0.0f);
}

// ---------------------------------------------------------------------------
// Main kernel: 128 blocks x 256 threads.
// Block -> (b, 8-row h tile, 16-col w tile). Warp -> one output row, all 64 f.
// Thread (lane l) owns filters f = 2l, 2l+1.
__global__ __launch_bounds__(256, 1)
void kan_main_kernel(const float* __restrict__ bias,
                     float* __restrict__ out)
{
    int bx   = blockIdx.x;
    int b    = bx >> 5;                 // 32 blocks per batch image
    int h0   = ((bx >> 2) & 7) * 8;
    int w0   = (bx & 3) * 16;
    int warp = threadIdx.x >> 5;
    int lane = threadIdx.x & 31;
    int h    = h0 + warp;

    float acc0[16], acc1[16];
#pragma unroll
    for (int p = 0; p < 16; p++) { acc0[p] = 0.0f; acc1[p] = 0.0f; }

    const float4* feat = g_feat;

    for (int c = 0; c < NC; c++) {
#pragma unroll
        for (int i = 0; i < 3; i++) {
            const float4* frow = feat + ((b * NH + h + i) * NW + w0) * NC + c;
#pragma unroll
            for (int j = 0; j < 3; j++) {
                int cij = c * 9 + i * 3 + j;
                const char* adbase =
                    (const char*)g_AD + (size_t)cij * (16 * 512) + lane * 16;
                float2 wsv = *(const float2*)(g_WS + cij * NF + 2 * lane);
                const float4* fp = frow + j * NC;
#pragma unroll
                for (int p = 0; p < 16; p++) {
                    float4 us = __ldg(fp + p * NC);      // (t, s, ofs, -) broadcast
                    const float4 ad =
                        *(const float4*)(adbase + __float_as_int(us.z));
                    // spline: A + t*D for the two owned filters
                    acc0[p] += fmaf(us.x, ad.y, ad.x);
                    acc1[p] += fmaf(us.x, ad.w, ad.z);
                    // silu branch
                    acc0[p] = fmaf(us.y, wsv.x, acc0[p]);
                    acc1[p] = fmaf(us.y, wsv.y, acc1[p]);
                }
            }
        }
    }

    float2 bv = *(const float2*)(bias + 2 * lane);
    float* op = out + (((b * HO) + h) * WO + w0) * NF + 2 * lane;
#pragma unroll
    for (int p = 0; p < 16; p++) {
        float2 r;
        r.x = acc0[p] + bv.x;
        r.y = acc1[p] + bv.y;
        *(float2*)(op + p * NF) = r;
    }
}

// ---------------------------------------------------------------------------
extern "C" void kernel_launch(void* const* d_in, const int* in_sizes, int n_in,
                              void* d_out, int out_size)
{
    const float* x    = (const float*)d_in[0];   // (4,66,66,32)
    const float* cp   = (const float*)d_in[1];   // (64,32,3,3,17)
    const float* wsp  = (const float*)d_in[2];   // (64,32,3,3)
    const float* wsi  = (const float*)d_in[3];   // (64,32,3,3)
    const float* bias = (const float*)d_in[4];   // (64,)
    float* out        = (float*)d_out;           // (4,64,64,64)

    {
        int n = CKK * 16 * NF;
        build_ad_kernel<<<(n + 255) / 256, 256>>>(cp, wsp);
    }
    {
        int n = CKK * NF;
        build_ws_kernel<<<(n + 255) / 256, 256>>>(wsi);
    }
    {
        int n = NB * NH * NW * NC;
        feat_kernel<<<(n + 255) / 256, 256>>>(x);
    }
    kan_main_kernel<<<128, 256>>>(bias, out);
}

// round 3
// speedup vs baseline: 1.7543x; 1.7519x over previous
#include <cuda_runtime.h>
#include <cuda_fp16.h>
#include <math.h>

// Problem constants
#define GRIDSZ 16
#define NB   4
#define NH   66
#define NW   66
#define NC   32
#define NF   64
#define HO   64
#define WO   64
#define CKK  288          // C*KH*KW = 32*9

// Scratch (device globals; no allocation allowed)
// AD table (fp16): [cij][g][f] -> (A, D) interleaved halves. 288*16*64*2 halves = 1.18 MB
__device__ __align__(16) __half g_AD16[CKK * 16 * NF * 2];
__device__ __align__(16) float  g_WS[CKK * NF];            // transposed w_silu [cij][f]
__device__ __align__(16) float4 g_feat[NB * NH * NW * NC]; // (t, silu, byteofs(g*256), 0)

// ---------------------------------------------------------------------------
// P0: build fp16 AD table.  tid -> f (6b), g (4b), cij (rest)
__global__ void build_ad_kernel(const float* __restrict__ cp,
                                const float* __restrict__ w_spline)
{
    int tid = blockIdx.x * blockDim.x + threadIdx.x;
    if (tid >= CKK * 16 * NF) return;
    int f   = tid & 63;
    int g   = (tid >> 6) & 15;
    int cij = tid >> 10;
    float ws = w_spline[f * CKK + cij];
    const float* cpp = cp + (size_t)f * (CKK * 17) + cij * 17 + g;
    float a0 = ws * cpp[0];
    float a1 = ws * cpp[1];
    size_t base = ((size_t)(cij * 16 + g) * NF + f) * 2;
    g_AD16[base]     = __float2half_rn(a0);
    g_AD16[base + 1] = __float2half_rn(a1 - a0);
}

// P0b: transpose w_silu into [cij][f]
__global__ void build_ws_kernel(const float* __restrict__ w_silu)
{
    int tid = blockIdx.x * blockDim.x + threadIdx.x;
    if (tid >= CKK * NF) return;
    int f   = tid & 63;
    int cij = tid >> 6;
    g_WS[cij * NF + f] = w_silu[f * CKK + cij];
}

// ---------------------------------------------------------------------------
// P1: per-input-element features: t, silu(x), byte offset g*256 into fp16 AD slice
__global__ void feat_kernel(const float* __restrict__ x)
{
    int i = blockIdx.x * blockDim.x + threadIdx.x;
    if (i >= NB * NH * NW * NC) return;
    float v  = x[i];
    float s  = v / (1.0f + __expf(-v));                 // SiLU
    float xc = fminf(1.0f, fmaxf(-1.0f, v));
    float u  = (xc + 1.0f) * 8.0f;                      // / (2/16)
    int   g  = (int)u;
    g = (g > 15) ? 15 : g;
    float t  = u - (float)g;
    g_feat[i] = make_float4(t, s, __int_as_float(g * 256), 0.0f);
}

// ---------------------------------------------------------------------------
// Main kernel: 256 blocks x 256 threads, 2 blocks/SM.
// Block -> (b, 8-row h tile, 8-col w tile). Warp -> one output row (8 px), all 64 f.
// Thread (lane l) owns filters f = 2l, 2l+1.
__global__ __launch_bounds__(256, 2)
void kan_main_kernel(const float* __restrict__ bias,
                     float* __restrict__ out)
{
    int bx   = blockIdx.x;
    int b    = bx >> 6;                 // 64 blocks per batch image
    int h0   = ((bx >> 3) & 7) * 8;
    int w0   = (bx & 7) * 8;
    int warp = threadIdx.x >> 5;
    int lane = threadIdx.x & 31;
    int h    = h0 + warp;

    float acc0[8], acc1[8];
#pragma unroll
    for (int p = 0; p < 8; p++) { acc0[p] = 0.0f; acc1[p] = 0.0f; }

    for (int c = 0; c < NC; c++) {
#pragma unroll
        for (int i = 0; i < 3; i++) {
            // 10 feature entries cover all (j, p) combos: index = p + j, p<8, j<3
            const float4* frow = g_feat + (((b * NH) + h + i) * NW + w0) * NC + c;
            float4 q[10];
#pragma unroll
            for (int m = 0; m < 10; m++) q[m] = __ldg(frow + m * NC);
#pragma unroll
            for (int j = 0; j < 3; j++) {
                int cij = c * 9 + i * 3 + j;
                const char* adbase =
                    (const char*)g_AD16 + (size_t)cij * (16 * 256) + lane * 8;
                float2 wsv = *(const float2*)(g_WS + cij * NF + 2 * lane);
#pragma unroll
                for (int p = 0; p < 8; p++) {
                    float4 us = q[p + j];                // (t, silu, g*256, -)
                    uint2 adu = *(const uint2*)(adbase + __float_as_int(us.z));
                    float2 f0 = __half22float2(*(const __half2*)&adu.x); // (A0,D0)
                    float2 f1 = __half22float2(*(const __half2*)&adu.y); // (A1,D1)
                    acc0[p] += fmaf(us.x, f0.y, f0.x);   // spline f=2l
                    acc1[p] += fmaf(us.x, f1.y, f1.x);   // spline f=2l+1
                    acc0[p] = fmaf(us.y, wsv.x, acc0[p]); // silu f=2l
                    acc1[p] = fmaf(us.y, wsv.y, acc1[p]); // silu f=2l+1
                }
            }
        }
    }

    float2 bv = *(const float2*)(bias + 2 * lane);
    float* op = out + (((b * HO) + h) * WO + w0) * NF + 2 * lane;
#pragma unroll
    for (int p = 0; p < 8; p++) {
        float2 r;
        r.x = acc0[p] + bv.x;
        r.y = acc1[p] + bv.y;
        *(float2*)(op + p * NF) = r;
    }
}

// ---------------------------------------------------------------------------
extern "C" void kernel_launch(void* const* d_in, const int* in_sizes, int n_in,
                              void* d_out, int out_size)
{
    const float* x    = (const float*)d_in[0];   // (4,66,66,32)
    const float* cp   = (const float*)d_in[1];   // (64,32,3,3,17)
    const float* wsp  = (const float*)d_in[2];   // (64,32,3,3)
    const float* wsi  = (const float*)d_in[3];   // (64,32,3,3)
    const float* bias = (const float*)d_in[4];   // (64,)
    float* out        = (float*)d_out;           // (4,64,64,64)

    {
        int n = CKK * 16 * NF;
        build_ad_kernel<<<(n + 255) / 256, 256>>>(cp, wsp);
    }
    {
        int n = CKK * NF;
        build_ws_kernel<<<(n + 255) / 256, 256>>>(wsi);
    }
    {
        int n = NB * NH * NW * NC;
        feat_kernel<<<(n + 255) / 256, 256>>>(x);
    }
    kan_main_kernel<<<256, 256>>>(bias, out);
}